// round 15
// baseline (speedup 1.0000x reference)
#include <cuda_runtime.h>

// AttentionConv: q,k,v = 1x1 convs; per-channel softmax over 7x7 window of
// q*(k+bias); out = sum attn*v.  B=4, C=Cout=64, H=W=64, K=7, PAD=3.
//
// R15: attn single-wave retile.  R14 (2048 x 128thr) hit the 8-block/SM cap
//      with a 1.73-wave tail.  Now 256 threads, 16-row tile, grid (4,64,4)
//      = 1024 blocks = 6.92 blocks/SM x 256 thr -> whole grid resident in
//      one wave (~55 warps/SM), thread still 1 row x 4 cols, 22-row halo.
//      qkv = R8 FFMA2 kernel verbatim (measured floor).

#define LOG2E 1.4426950408889634f

__device__ float g_q[4 * 64 * 64 * 64];
__device__ float g_k[4 * 64 * 64 * 64];
__device__ float g_v[4 * 64 * 64 * 64];

__device__ __forceinline__ float ex2f(float v) {
    float r;
    asm("ex2.approx.ftz.f32 %0, %1;" : "=f"(r) : "f"(v));
    return r;
}

__device__ __forceinline__ unsigned long long fma_f32x2(
    unsigned long long a, unsigned long long b, unsigned long long c) {
    unsigned long long d;
    asm("fma.rn.f32x2 %0, %1, %2, %3;" : "=l"(d) : "l"(a), "l"(b), "l"(c));
    return d;
}

__device__ __forceinline__ unsigned long long dupf(float v) {
    unsigned long long r;
    asm("mov.b64 %0, {%1, %1};" : "=l"(r) : "f"(v));
    return r;
}

// ---------------------------------------------------------------------------
// Kernel 1: qkv projections (R8 version verbatim).  128 threads,
// 64oc x 64px tile, 768 blocks.  ws[c][o] = W^T stride 66; xs[c][p].
// Thread tile 8oc x 4px as 4 o-pairs, FFMA2.
// ---------------------------------------------------------------------------
#define WSTR 66

__global__ __launch_bounds__(128) void qkv_kernel(
    const float* __restrict__ x, const float* __restrict__ y,
    const float* __restrict__ Wq, const float* __restrict__ Wk,
    const float* __restrict__ Wv) {
    __shared__ __align__(16) float ws[64 * WSTR];
    __shared__ __align__(16) float xs[64 * 64];

    const int mat = blockIdx.y;
    const float* Wsrc = (mat == 0) ? Wq : ((mat == 1) ? Wk : Wv);
    const float* src  = (mat == 2) ? y : x;
    float* dst = (mat == 0) ? g_q : ((mat == 1) ? g_k : g_v);

    const int tid = threadIdx.x;
    const int pix0 = blockIdx.x * 64;
    const int b = pix0 >> 12;
    const int hw0 = pix0 & 4095;

#pragma unroll
    for (int i = 0; i < 32; i++) {
        int idx = tid + i * 128;           // = o*64 + c
        ws[(idx & 63) * WSTR + (idx >> 6)] = Wsrc[idx];
    }
#pragma unroll
    for (int i = 0; i < 32; i++) {
        int idx = tid + i * 128;           // = c*64 + p
        xs[idx] = src[((b << 6) + (idx >> 6)) * 4096 + hw0 + (idx & 63)];
    }
    __syncthreads();

    const int o0 = (tid >> 4) << 3;
    const int p0 = (tid & 15) << 2;

    unsigned long long acc[4][4];
#pragma unroll
    for (int i = 0; i < 4; i++)
#pragma unroll
        for (int j = 0; j < 4; j++) acc[i][j] = 0ULL;

#pragma unroll 4
    for (int cc = 0; cc < 64; cc++) {
        float4 xv = *(const float4*)(xs + (cc << 6) + p0);
        unsigned long long dx0 = dupf(xv.x);
        unsigned long long dx1 = dupf(xv.y);
        unsigned long long dx2 = dupf(xv.z);
        unsigned long long dx3 = dupf(xv.w);
        const float* wrow = ws + cc * WSTR + o0;
        unsigned long long wp0 = *(const unsigned long long*)(wrow);
        unsigned long long wp1 = *(const unsigned long long*)(wrow + 2);
        unsigned long long wp2 = *(const unsigned long long*)(wrow + 4);
        unsigned long long wp3 = *(const unsigned long long*)(wrow + 6);
        acc[0][0] = fma_f32x2(wp0, dx0, acc[0][0]);
        acc[0][1] = fma_f32x2(wp0, dx1, acc[0][1]);
        acc[0][2] = fma_f32x2(wp0, dx2, acc[0][2]);
        acc[0][3] = fma_f32x2(wp0, dx3, acc[0][3]);
        acc[1][0] = fma_f32x2(wp1, dx0, acc[1][0]);
        acc[1][1] = fma_f32x2(wp1, dx1, acc[1][1]);
        acc[1][2] = fma_f32x2(wp1, dx2, acc[1][2]);
        acc[1][3] = fma_f32x2(wp1, dx3, acc[1][3]);
        acc[2][0] = fma_f32x2(wp2, dx0, acc[2][0]);
        acc[2][1] = fma_f32x2(wp2, dx1, acc[2][1]);
        acc[2][2] = fma_f32x2(wp2, dx2, acc[2][2]);
        acc[2][3] = fma_f32x2(wp2, dx3, acc[2][3]);
        acc[3][0] = fma_f32x2(wp3, dx0, acc[3][0]);
        acc[3][1] = fma_f32x2(wp3, dx1, acc[3][1]);
        acc[3][2] = fma_f32x2(wp3, dx2, acc[3][2]);
        acc[3][3] = fma_f32x2(wp3, dx3, acc[3][3]);
    }

#pragma unroll
    for (int o2 = 0; o2 < 4; o2++) {
        float2 v0 = *reinterpret_cast<float2*>(&acc[o2][0]);
        float2 v1 = *reinterpret_cast<float2*>(&acc[o2][1]);
        float2 v2 = *reinterpret_cast<float2*>(&acc[o2][2]);
        float2 v3 = *reinterpret_cast<float2*>(&acc[o2][3]);
        float* base = dst + ((b << 6) + o0 + 2 * o2) * 4096 + hw0 + p0;
        *(float4*)(base)        = make_float4(v0.x, v1.x, v2.x, v3.x);
        *(float4*)(base + 4096) = make_float4(v0.y, v1.y, v2.y, v3.y);
    }
}

// ---------------------------------------------------------------------------
// Kernel 2: windowed per-channel softmax-attention.
// grid = (4 h-tiles, 64 channels, 4 batches) = 1024 blocks; 256 threads.
// Block: 16 rows x 64 cols; thread: 1 row x 4 cols (ty=tid>>4: 0..15);
// 22-row halo, stride 76.  Whole grid resident in one wave (~7 blk/SM).
// ---------------------------------------------------------------------------
#define KSW 76

__global__ __launch_bounds__(256, 7) void attn_kernel(
    const float* __restrict__ rel_h, const float* __restrict__ rel_w,
    float* __restrict__ out) {
    __shared__ __align__(16) float ks[22 * KSW];
    __shared__ __align__(16) float vs[22 * KSW];

    const int tid = threadIdx.x;
    const int h0 = blockIdx.x << 4;        // 16-row tile
    const int c  = blockIdx.y;
    const int b  = blockIdx.z;
    const int plane = ((b << 6) + c) << 12;

    const int ty = tid >> 4;               // 0..15 output row in tile
    const int w0 = (tid & 15) << 2;        // 4 outputs along w
    const int r0 = h0 + ty;

    // ---- issue ALL global loads up front ----
    const float* kp = g_k + plane;
    const float* vp = g_v + plane;
    float4 kreg[2], vreg[2];
    bool inb[2];
    int soff[2];
#pragma unroll
    for (int it = 0; it < 2; it++) {
        int i = tid + it * 256;            // 0..351 (22 rows x 16 col-groups)
        int r = i >> 4, c4 = (i & 15) << 2;
        int gr = h0 - 3 + r;
        bool valid = (i < 352) && ((unsigned)gr < 64u);
        inb[it] = valid;
        soff[it] = r * KSW + 3 + c4;
        if (valid) {
            kreg[it] = *(const float4*)(kp + (gr << 6) + c4);
            vreg[it] = *(const float4*)(vp + (gr << 6) + c4);
        }
    }
    const float4 q4 = *(const float4*)(g_q + plane + (r0 << 6) + w0);

    const float* bp = (c < 32) ? (rel_h + c * 7) : (rel_w + (c - 32) * 7);
    float bias7[7];
#pragma unroll
    for (int j = 0; j < 7; j++) bias7[j] = __ldg(bp + j);

    // ---- zero ONLY the pad regions ----
    // side pads: cols 0-2 and 67-75 for all 22 rows (12 x 22 = 264)
    for (int i = tid; i < 264; i += 256) {
        int r = i / 12, cc = i % 12;
        int col = (cc < 3) ? cc : (64 + cc);   // 3..11 -> 67..75
        ks[r * KSW + col] = 0.0f;
        vs[r * KSW + col] = 0.0f;
    }
    // out-of-range halo rows: h0=0 -> rows 0-2; h0=48 -> rows 19-21
    if (h0 == 0) {
        for (int i = tid; i < 3 * KSW; i += 256) { ks[i] = 0.0f; vs[i] = 0.0f; }
    } else if (h0 == 48) {
        for (int i = tid; i < 3 * KSW; i += 256) {
            ks[19 * KSW + i] = 0.0f;
            vs[19 * KSW + i] = 0.0f;
        }
    }

    // ---- commit interior values ----
#pragma unroll
    for (int it = 0; it < 2; it++) {
        if (inb[it]) {
            int s0 = soff[it];
            ks[s0] = kreg[it].x; ks[s0 + 1] = kreg[it].y;
            ks[s0 + 2] = kreg[it].z; ks[s0 + 3] = kreg[it].w;
            vs[s0] = vreg[it].x; vs[s0 + 1] = vreg[it].y;
            vs[s0 + 2] = vreg[it].z; vs[s0 + 3] = vreg[it].w;
        }
    }
    __syncthreads();

    float q2[4] = {q4.x * LOG2E, q4.y * LOG2E, q4.z * LOG2E, q4.w * LOG2E};
    float s[4] = {0.f, 0.f, 0.f, 0.f};
    float a[4] = {0.f, 0.f, 0.f, 0.f};

    if (c < 32) {
        // bias depends on kh only: hoist q2*bias out of the kw loop
#pragma unroll
        for (int j = 0; j < 7; j++) {
            const float* krow = &ks[(ty + j) * KSW + w0];
            const float* vrow = &vs[(ty + j) * KSW + w0];
            float kr[12], vr[12];
            *(float4*)(kr)     = *(const float4*)(krow);
            *(float4*)(kr + 4) = *(const float4*)(krow + 4);
            *(float4*)(kr + 8) = *(const float4*)(krow + 8);
            *(float4*)(vr)     = *(const float4*)(vrow);
            *(float4*)(vr + 4) = *(const float4*)(vrow + 4);
            *(float4*)(vr + 8) = *(const float4*)(vrow + 8);
            float qb0[4];
#pragma unroll
            for (int i = 0; i < 4; i++) qb0[i] = q2[i] * bias7[j];
#pragma unroll
            for (int kw = 0; kw < 7; kw++)
#pragma unroll
                for (int i = 0; i < 4; i++) {
                    float e = ex2f(fmaf(q2[i], kr[i + kw], qb0[i]));
                    s[i] += e;
                    a[i] = fmaf(e, vr[i + kw], a[i]);
                }
        }
    } else {
        // bias depends on kw only
#pragma unroll
        for (int j = 0; j < 7; j++) {
            const float* krow = &ks[(ty + j) * KSW + w0];
            const float* vrow = &vs[(ty + j) * KSW + w0];
            float kr[12], vr[12];
            *(float4*)(kr)     = *(const float4*)(krow);
            *(float4*)(kr + 4) = *(const float4*)(krow + 4);
            *(float4*)(kr + 8) = *(const float4*)(krow + 8);
            *(float4*)(vr)     = *(const float4*)(vrow);
            *(float4*)(vr + 4) = *(const float4*)(vrow + 4);
            *(float4*)(vr + 8) = *(const float4*)(vrow + 8);
#pragma unroll
            for (int kw = 0; kw < 7; kw++) {
                float bb = bias7[kw];
#pragma unroll
                for (int i = 0; i < 4; i++) {
                    float e = ex2f(q2[i] * (kr[i + kw] + bb));
                    s[i] += e;
                    a[i] = fmaf(e, vr[i + kw], a[i]);
                }
            }
        }
    }

    float4 o4;
    o4.x = __fdividef(a[0], s[0]);
    o4.y = __fdividef(a[1], s[1]);
    o4.z = __fdividef(a[2], s[2]);
    o4.w = __fdividef(a[3], s[3]);
    *(float4*)(out + plane + (r0 << 6) + w0) = o4;
}

extern "C" void kernel_launch(void* const* d_in, const int* in_sizes, int n_in,
                              void* d_out, int out_size) {
    const float* x     = (const float*)d_in[0];
    const float* y     = (const float*)d_in[1];
    const float* Wq    = (const float*)d_in[2];
    const float* Wk    = (const float*)d_in[3];
    const float* Wv    = (const float*)d_in[4];
    const float* rel_h = (const float*)d_in[5];
    const float* rel_w = (const float*)d_in[6];
    float* out = (float*)d_out;

    dim3 g1(256, 3, 1);
    qkv_kernel<<<g1, 128>>>(x, y, Wq, Wk, Wv);

    dim3 g2(4, 64, 4);
    attn_kernel<<<g2, 256>>>(rel_h, rel_w, out);
}

// round 16
// speedup vs baseline: 1.0932x; 1.0932x over previous
#include <cuda_runtime.h>

// AttentionConv: q,k,v = 1x1 convs; per-channel softmax over 7x7 window of
// q*(k+bias); out = sum attn*v.  B=4, C=Cout=64, H=W=64, K=7, PAD=3.
//
// R16: R14 (best: 26.5us) with ONE change: attn __launch_bounds__(128,8) ->
//      (128,9).  regs=56 fits 9 blocks/SM exactly (65536/(128*56)=9.14,
//      smem 9.1KB*9=82KB), so the 8-block cap was self-imposed.  R15's
//      256-thr variant proved regs<56 destroys the register-resident
//      strips (L1 26->41%, issue 72->55) -- occupancy must not cost regs.
//      qkv = R8 FFMA2 kernel verbatim (measured floor 12.0-12.3us).

#define LOG2E 1.4426950408889634f

__device__ float g_q[4 * 64 * 64 * 64];
__device__ float g_k[4 * 64 * 64 * 64];
__device__ float g_v[4 * 64 * 64 * 64];

__device__ __forceinline__ float ex2f(float v) {
    float r;
    asm("ex2.approx.ftz.f32 %0, %1;" : "=f"(r) : "f"(v));
    return r;
}

__device__ __forceinline__ unsigned long long fma_f32x2(
    unsigned long long a, unsigned long long b, unsigned long long c) {
    unsigned long long d;
    asm("fma.rn.f32x2 %0, %1, %2, %3;" : "=l"(d) : "l"(a), "l"(b), "l"(c));
    return d;
}

__device__ __forceinline__ unsigned long long dupf(float v) {
    unsigned long long r;
    asm("mov.b64 %0, {%1, %1};" : "=l"(r) : "f"(v));
    return r;
}

// ---------------------------------------------------------------------------
// Kernel 1: qkv projections (R8 version verbatim).  128 threads,
// 64oc x 64px tile, 768 blocks.  ws[c][o] = W^T stride 66; xs[c][p].
// Thread tile 8oc x 4px as 4 o-pairs, FFMA2.
// ---------------------------------------------------------------------------
#define WSTR 66

__global__ __launch_bounds__(128) void qkv_kernel(
    const float* __restrict__ x, const float* __restrict__ y,
    const float* __restrict__ Wq, const float* __restrict__ Wk,
    const float* __restrict__ Wv) {
    __shared__ __align__(16) float ws[64 * WSTR];
    __shared__ __align__(16) float xs[64 * 64];

    const int mat = blockIdx.y;
    const float* Wsrc = (mat == 0) ? Wq : ((mat == 1) ? Wk : Wv);
    const float* src  = (mat == 2) ? y : x;
    float* dst = (mat == 0) ? g_q : ((mat == 1) ? g_k : g_v);

    const int tid = threadIdx.x;
    const int pix0 = blockIdx.x * 64;
    const int b = pix0 >> 12;
    const int hw0 = pix0 & 4095;

#pragma unroll
    for (int i = 0; i < 32; i++) {
        int idx = tid + i * 128;           // = o*64 + c
        ws[(idx & 63) * WSTR + (idx >> 6)] = Wsrc[idx];
    }
#pragma unroll
    for (int i = 0; i < 32; i++) {
        int idx = tid + i * 128;           // = c*64 + p
        xs[idx] = src[((b << 6) + (idx >> 6)) * 4096 + hw0 + (idx & 63)];
    }
    __syncthreads();

    const int o0 = (tid >> 4) << 3;
    const int p0 = (tid & 15) << 2;

    unsigned long long acc[4][4];
#pragma unroll
    for (int i = 0; i < 4; i++)
#pragma unroll
        for (int j = 0; j < 4; j++) acc[i][j] = 0ULL;

#pragma unroll 4
    for (int cc = 0; cc < 64; cc++) {
        float4 xv = *(const float4*)(xs + (cc << 6) + p0);
        unsigned long long dx0 = dupf(xv.x);
        unsigned long long dx1 = dupf(xv.y);
        unsigned long long dx2 = dupf(xv.z);
        unsigned long long dx3 = dupf(xv.w);
        const float* wrow = ws + cc * WSTR + o0;
        unsigned long long wp0 = *(const unsigned long long*)(wrow);
        unsigned long long wp1 = *(const unsigned long long*)(wrow + 2);
        unsigned long long wp2 = *(const unsigned long long*)(wrow + 4);
        unsigned long long wp3 = *(const unsigned long long*)(wrow + 6);
        acc[0][0] = fma_f32x2(wp0, dx0, acc[0][0]);
        acc[0][1] = fma_f32x2(wp0, dx1, acc[0][1]);
        acc[0][2] = fma_f32x2(wp0, dx2, acc[0][2]);
        acc[0][3] = fma_f32x2(wp0, dx3, acc[0][3]);
        acc[1][0] = fma_f32x2(wp1, dx0, acc[1][0]);
        acc[1][1] = fma_f32x2(wp1, dx1, acc[1][1]);
        acc[1][2] = fma_f32x2(wp1, dx2, acc[1][2]);
        acc[1][3] = fma_f32x2(wp1, dx3, acc[1][3]);
        acc[2][0] = fma_f32x2(wp2, dx0, acc[2][0]);
        acc[2][1] = fma_f32x2(wp2, dx1, acc[2][1]);
        acc[2][2] = fma_f32x2(wp2, dx2, acc[2][2]);
        acc[2][3] = fma_f32x2(wp2, dx3, acc[2][3]);
        acc[3][0] = fma_f32x2(wp3, dx0, acc[3][0]);
        acc[3][1] = fma_f32x2(wp3, dx1, acc[3][1]);
        acc[3][2] = fma_f32x2(wp3, dx2, acc[3][2]);
        acc[3][3] = fma_f32x2(wp3, dx3, acc[3][3]);
    }

#pragma unroll
    for (int o2 = 0; o2 < 4; o2++) {
        float2 v0 = *reinterpret_cast<float2*>(&acc[o2][0]);
        float2 v1 = *reinterpret_cast<float2*>(&acc[o2][1]);
        float2 v2 = *reinterpret_cast<float2*>(&acc[o2][2]);
        float2 v3 = *reinterpret_cast<float2*>(&acc[o2][3]);
        float* base = dst + ((b << 6) + o0 + 2 * o2) * 4096 + hw0 + p0;
        *(float4*)(base)        = make_float4(v0.x, v1.x, v2.x, v3.x);
        *(float4*)(base + 4096) = make_float4(v0.y, v1.y, v2.y, v3.y);
    }
}

// ---------------------------------------------------------------------------
// Kernel 2: windowed per-channel softmax-attention (R14 + 9 blocks/SM).
// grid = (8 h-tiles, 64 channels, 4 batches) = 2048 blocks; 128 threads.
// Block: 8 rows x 64 cols; thread: 1 row x 4 cols; 14-row halo (stride 76).
// Hoisted LDG (2 predicated float4-pairs/thread), pad-only zero-fill.
// ---------------------------------------------------------------------------
#define KSW 76

__global__ __launch_bounds__(128, 9) void attn_kernel(
    const float* __restrict__ rel_h, const float* __restrict__ rel_w,
    float* __restrict__ out) {
    __shared__ __align__(16) float ks[14 * KSW];
    __shared__ __align__(16) float vs[14 * KSW];

    const int tid = threadIdx.x;
    const int h0 = blockIdx.x << 3;        // 8-row tile
    const int c  = blockIdx.y;
    const int b  = blockIdx.z;
    const int plane = ((b << 6) + c) << 12;

    const int ty = tid >> 4;               // 0..7 output row in tile
    const int w0 = (tid & 15) << 2;        // 4 outputs along w
    const int r0 = h0 + ty;

    // ---- issue ALL global loads up front ----
    const float* kp = g_k + plane;
    const float* vp = g_v + plane;
    float4 kreg[2], vreg[2];
    bool inb[2];
    int soff[2];
#pragma unroll
    for (int it = 0; it < 2; it++) {
        int i = tid + it * 128;            // 0..223 (14 rows x 16 col-groups)
        int r = i >> 4, c4 = (i & 15) << 2;
        int gr = h0 - 3 + r;
        bool valid = (i < 224) && ((unsigned)gr < 64u);
        inb[it] = valid;
        soff[it] = r * KSW + 3 + c4;
        if (valid) {
            kreg[it] = *(const float4*)(kp + (gr << 6) + c4);
            vreg[it] = *(const float4*)(vp + (gr << 6) + c4);
        }
    }
    const float4 q4 = *(const float4*)(g_q + plane + (r0 << 6) + w0);

    const float* bp = (c < 32) ? (rel_h + c * 7) : (rel_w + (c - 32) * 7);
    float bias7[7];
#pragma unroll
    for (int j = 0; j < 7; j++) bias7[j] = __ldg(bp + j);

    // ---- zero ONLY the pad regions ----
    // side pads: cols 0-2 and 67-75 for all 14 rows (12 x 14 = 168)
    for (int i = tid; i < 168; i += 128) {
        int r = i / 12, cc = i % 12;
        int col = (cc < 3) ? cc : (64 + cc);   // 3..11 -> 67..75
        ks[r * KSW + col] = 0.0f;
        vs[r * KSW + col] = 0.0f;
    }
    // out-of-range halo rows: h0=0 -> rows 0-2; h0=56 -> rows 11-13
    if (h0 == 0) {
        for (int i = tid; i < 3 * KSW; i += 128) { ks[i] = 0.0f; vs[i] = 0.0f; }
    } else if (h0 == 56) {
        for (int i = tid; i < 3 * KSW; i += 128) {
            ks[11 * KSW + i] = 0.0f;
            vs[11 * KSW + i] = 0.0f;
        }
    }

    // ---- commit interior values ----
#pragma unroll
    for (int it = 0; it < 2; it++) {
        if (inb[it]) {
            int s0 = soff[it];
            ks[s0] = kreg[it].x; ks[s0 + 1] = kreg[it].y;
            ks[s0 + 2] = kreg[it].z; ks[s0 + 3] = kreg[it].w;
            vs[s0] = vreg[it].x; vs[s0 + 1] = vreg[it].y;
            vs[s0 + 2] = vreg[it].z; vs[s0 + 3] = vreg[it].w;
        }
    }
    __syncthreads();

    float q2[4] = {q4.x * LOG2E, q4.y * LOG2E, q4.z * LOG2E, q4.w * LOG2E};
    float s[4] = {0.f, 0.f, 0.f, 0.f};
    float a[4] = {0.f, 0.f, 0.f, 0.f};

    if (c < 32) {
        // bias depends on kh only: hoist q2*bias out of the kw loop
#pragma unroll
        for (int j = 0; j < 7; j++) {
            const float* krow = &ks[(ty + j) * KSW + w0];
            const float* vrow = &vs[(ty + j) * KSW + w0];
            float kr[12], vr[12];
            *(float4*)(kr)     = *(const float4*)(krow);
            *(float4*)(kr + 4) = *(const float4*)(krow + 4);
            *(float4*)(kr + 8) = *(const float4*)(krow + 8);
            *(float4*)(vr)     = *(const float4*)(vrow);
            *(float4*)(vr + 4) = *(const float4*)(vrow + 4);
            *(float4*)(vr + 8) = *(const float4*)(vrow + 8);
            float qb0[4];
#pragma unroll
            for (int i = 0; i < 4; i++) qb0[i] = q2[i] * bias7[j];
#pragma unroll
            for (int kw = 0; kw < 7; kw++)
#pragma unroll
                for (int i = 0; i < 4; i++) {
                    float e = ex2f(fmaf(q2[i], kr[i + kw], qb0[i]));
                    s[i] += e;
                    a[i] = fmaf(e, vr[i + kw], a[i]);
                }
        }
    } else {
        // bias depends on kw only
#pragma unroll
        for (int j = 0; j < 7; j++) {
            const float* krow = &ks[(ty + j) * KSW + w0];
            const float* vrow = &vs[(ty + j) * KSW + w0];
            float kr[12], vr[12];
            *(float4*)(kr)     = *(const float4*)(krow);
            *(float4*)(kr + 4) = *(const float4*)(krow + 4);
            *(float4*)(kr + 8) = *(const float4*)(krow + 8);
            *(float4*)(vr)     = *(const float4*)(vrow);
            *(float4*)(vr + 4) = *(const float4*)(vrow + 4);
            *(float4*)(vr + 8) = *(const float4*)(vrow + 8);
#pragma unroll
            for (int kw = 0; kw < 7; kw++) {
                float bb = bias7[kw];
#pragma unroll
                for (int i = 0; i < 4; i++) {
                    float e = ex2f(q2[i] * (kr[i + kw] + bb));
                    s[i] += e;
                    a[i] = fmaf(e, vr[i + kw], a[i]);
                }
            }
        }
    }

    float4 o4;
    o4.x = __fdividef(a[0], s[0]);
    o4.y = __fdividef(a[1], s[1]);
    o4.z = __fdividef(a[2], s[2]);
    o4.w = __fdividef(a[3], s[3]);
    *(float4*)(out + plane + (r0 << 6) + w0) = o4;
}

extern "C" void kernel_launch(void* const* d_in, const int* in_sizes, int n_in,
                              void* d_out, int out_size) {
    const float* x     = (const float*)d_in[0];
    const float* y     = (const float*)d_in[1];
    const float* Wq    = (const float*)d_in[2];
    const float* Wk    = (const float*)d_in[3];
    const float* Wv    = (const float*)d_in[4];
    const float* rel_h = (const float*)d_in[5];
    const float* rel_w = (const float*)d_in[6];
    float* out = (float*)d_out;

    dim3 g1(256, 3, 1);
    qkv_kernel<<<g1, 128>>>(x, y, Wq, Wk, Wv);

    dim3 g2(8, 64, 4);
    attn_kernel<<<g2, 128>>>(rel_h, rel_w, out);
}